// round 3
// baseline (speedup 1.0000x reference)
#include <cuda_runtime.h>
#include <math.h>

// ---------------- static scratch ----------------
#define NSP 524288            // 32*32*32*16 points per (b,c)
#define NCH 20
#define NB  2
#define NMODE 24576           // 16*16*16*6 kept modes

__device__ float  g_hA[NB*NCH*NSP];          // 84 MB
__device__ float  g_hB[NB*NCH*NSP];          // 84 MB
__device__ float2 g_fa[NB*NCH*16*6*1024];    // 31.5 MB : S1 [bc][kz*6+kt][x*32+y]
__device__ float2 g_fb[NB*NCH*16*6*1024];    // 31.5 MB : S2 [bo][kx*6+kt][y*32+z]
__device__ float2 g_fd[NB*NCH*NMODE];        // x_ft   at kept modes
__device__ float2 g_fe[NB*NCH*NMODE];        // out_ft at kept modes

// twiddle tables
__device__ float2 d_fwdX[512];   // [m(16)][x(32)]  e^{-2pi i k_m x/32},  k_m = m + (m>=8)*16
__device__ float2 d_fwdT[96];    // [k(6)][t(16)]   e^{-2pi i k t/16}
__device__ float2 d_invX[512];   // [x(32)][m(16)]  (1/32) e^{+2pi i k_m x/32}
__device__ float2 d_invT[96];    // [t(16)][k(6)]   ((k==0?1:2)/16) * (cos, sin)(+2pi k t/16)

__device__ __forceinline__ float gelu_exact(float v) {
    return 0.5f * v * (1.0f + erff(v * 0.70710678118654752f));
}

// ---------------- init twiddles -------------------------------------------
__global__ void k_init() {
    int tid = threadIdx.x;
    if (tid < 512) {
        int m = tid >> 5, x = tid & 31;
        int k = m + (m >= 8 ? 16 : 0);
        int ph = (k * x) & 31;
        float s, c; sincospif(-(float)ph / 16.0f, &s, &c);
        d_fwdX[tid] = make_float2(c, s);

        int z = tid >> 4, mm = tid & 15;
        int k2 = mm + (mm >= 8 ? 16 : 0);
        int ph2 = (k2 * z) & 31;
        float s2, c2; sincospif((float)ph2 / 16.0f, &s2, &c2);
        d_invX[tid] = make_float2(c2 * (1.0f/32.0f), s2 * (1.0f/32.0f));
    }
    if (tid < 96) {
        int k = tid / 16, t = tid & 15;
        int ph = (k * t) & 15;
        float s, c; sincospif(-(float)ph / 8.0f, &s, &c);
        d_fwdT[tid] = make_float2(c, s);

        int t2 = tid / 6, k2 = tid % 6;
        int ph2 = (k2 * t2) & 15;
        float wk = (k2 == 0 ? 1.0f : 2.0f) * (1.0f/16.0f);
        float s2, c2; sincospif((float)ph2 / 8.0f, &s2, &c2);
        d_invT[tid] = make_float2(wk * c2, wk * s2);
    }
}

// ---------------- lift ------------------------------------------------------
__global__ void __launch_bounds__(256) k_lift(const float* __restrict__ x,
                                              const float* __restrict__ w,
                                              const float* __restrict__ bias) {
    int tid = blockIdx.x * blockDim.x + threadIdx.x;
    if (tid >= NB * NSP) return;
    int b = tid / NSP, p = tid % NSP;
    float xi[5];
#pragma unroll
    for (int i = 0; i < 5; i++) xi[i] = x[(size_t)tid * 5 + i];
#pragma unroll
    for (int c = 0; c < NCH; c++) {
        float a = __ldg(&bias[c]);
#pragma unroll
        for (int i = 0; i < 5; i++) a += xi[i] * __ldg(&w[i * NCH + c]);
        g_hA[(size_t)(b * NCH + c) * NSP + p] = a;
    }
}

// ---------------- fwd T (16->6) + Z (32->16) fused -------------------------
// block = (bc, x, yq) ; 256 threads = (yl 8, z 32)
__global__ void __launch_bounds__(256) k_fwdTZ(int src) {
    __shared__ float2 st[8 * 6 * 33];            // [yl][kt][z] padded
    const float* h = src ? g_hB : g_hA;
    int bid = blockIdx.x;
    int yq = bid & 3, x = (bid >> 2) & 31, bc = bid >> 7;
    int tid = threadIdx.x;
    int yl = tid >> 5, z = tid & 31;

    const float* p = h + (size_t)bc * NSP + x * 16384 + (yq * 8 + yl) * 512 + z * 16;
    float v[16];
#pragma unroll
    for (int t = 0; t < 16; t++) v[t] = p[t];
#pragma unroll
    for (int k = 0; k < 6; k++) {
        float2 a = make_float2(0.f, 0.f);
#pragma unroll
        for (int t = 0; t < 16; t++) {
            float2 w = d_fwdT[k * 16 + t];
            a.x += v[t] * w.x; a.y += v[t] * w.y;
        }
        st[(yl * 6 + k) * 33 + z] = a;
    }
    __syncthreads();

#pragma unroll
    for (int w = tid; w < 768; w += 256) {
        int yl2 = w & 7; int kk = w >> 3;        // kk = kz*6+kt
        int kt = kk % 6, kz = kk / 6;
        const float2* row = &st[(yl2 * 6 + kt) * 33];
        float2 acc = make_float2(0.f, 0.f);
#pragma unroll
        for (int zz = 0; zz < 32; zz++) {
            float2 g = row[zz]; float2 tw = d_fwdX[kz * 32 + zz];
            acc.x += g.x * tw.x - g.y * tw.y;
            acc.y += g.x * tw.y + g.y * tw.x;
        }
        g_fa[((size_t)(bc * 96) + kk) * 1024 + x * 32 + yq * 8 + yl2] = acc;
    }
}

// ---------------- fwd Y (32->16) + X (32->16) fused -------------------------
// block = (bc, kz, kt) = S1 slab ; 256 threads
__global__ void __launch_bounds__(256) k_fwdYX() {
    __shared__ float2 P[1024];   // [x][y]
    __shared__ float2 Q[512];    // [x][ky]
    int bid = blockIdx.x;                        // = bc*96 + kz*6+kt
    int tid = threadIdx.x;
    const float2* s1 = g_fa + (size_t)bid * 1024;
#pragma unroll
    for (int q = 0; q < 4; q++) P[tid + q * 256] = s1[tid + q * 256];
    __syncthreads();

#pragma unroll
    for (int u = tid; u < 512; u += 256) {
        int x = u >> 4, ky = u & 15;
        float2 acc = make_float2(0.f, 0.f);
#pragma unroll
        for (int y = 0; y < 32; y++) {
            float2 g = P[x * 32 + y]; float2 tw = d_fwdX[ky * 32 + y];
            acc.x += g.x * tw.x - g.y * tw.y;
            acc.y += g.x * tw.y + g.y * tw.x;
        }
        Q[u] = acc;
    }
    __syncthreads();

    {
        int u = tid;                             // u = kx*16+ky
        float2 acc = make_float2(0.f, 0.f);
        int ky = u & 15, kx = u >> 4;
#pragma unroll
        for (int x = 0; x < 32; x++) {
            float2 g = Q[x * 16 + ky]; float2 tw = d_fwdX[kx * 32 + x];
            acc.x += g.x * tw.x - g.y * tw.y;
            acc.y += g.x * tw.y + g.y * tw.x;
        }
        int kzkt = bid % 96; int bc = bid / 96;
        g_fd[(size_t)bc * NMODE + (size_t)u * 96 + kzkt] = acc;
    }
}

// ---------------- spectral channel mix --------------------------------------
// grid (96, 4): blockIdx.y selects 5 output channels
__global__ void __launch_bounds__(256) k_mult(const float2* __restrict__ swl) {
    int m = blockIdx.x * 256 + threadIdx.x;
    int ob = blockIdx.y * 5;
    int kt = m % 6; int r = m / 6;
    int kz = r & 15, ky = (r >> 4) & 15, kx = (r >> 8) & 15;
    int oct = ((kx >> 3) << 2) | ((ky >> 3) << 1) | (kz >> 3);
    int lm = (((kx & 7) * 8 + (ky & 7)) * 8 + (kz & 7)) * 6 + kt;
    const float2* wbase = swl + (size_t)oct * 1228800 + lm + (size_t)ob * 3072;

    float2 a0[5], a1[5];
#pragma unroll
    for (int o = 0; o < 5; o++) { a0[o] = make_float2(0.f,0.f); a1[o] = make_float2(0.f,0.f); }

    for (int i = 0; i < NCH; i++) {
        float2 x0 = __ldg(&g_fd[(size_t)i * NMODE + m]);
        float2 x1 = __ldg(&g_fd[(size_t)(NCH + i) * NMODE + m]);
        const float2* wp = wbase + (size_t)i * 61440;
#pragma unroll
        for (int o = 0; o < 5; o++) {
            float2 w = __ldg(&wp[o * 3072]);
            a0[o].x += w.x * x0.x - w.y * x0.y;
            a0[o].y += w.x * x0.y + w.y * x0.x;
            a1[o].x += w.x * x1.x - w.y * x1.y;
            a1[o].y += w.x * x1.y + w.y * x1.x;
        }
    }
#pragma unroll
    for (int o = 0; o < 5; o++) {
        g_fe[(size_t)(ob + o) * NMODE + m]        = a0[o];
        g_fe[(size_t)(NCH + ob + o) * NMODE + m]  = a1[o];
    }
}

// ---------------- inv Z (16->32) + Y (16->32) fused --------------------------
// block = (bo, kx, kt) ; 256 threads
__global__ void __launch_bounds__(256) k_invZY() {
    __shared__ float2 Gs[256];   // [ky][kz]
    __shared__ float2 H1[512];   // [y][kz]
    int bid = blockIdx.x;                         // = bo*96 + kx*6+kt
    int bo = bid / 96; int rr = bid % 96;
    int kx = rr / 6, kt = rr % 6;
    int tid = threadIdx.x;

    Gs[tid] = g_fe[(size_t)bo * NMODE + (size_t)(kx * 256 + tid) * 6 + kt];
    __syncthreads();

#pragma unroll
    for (int u = tid; u < 512; u += 256) {
        int y = u >> 4, kz = u & 15;
        float2 acc = make_float2(0.f, 0.f);
#pragma unroll
        for (int ky = 0; ky < 16; ky++) {
            float2 g = Gs[ky * 16 + kz]; float2 tw = d_invX[y * 16 + ky];
            acc.x += g.x * tw.x - g.y * tw.y;
            acc.y += g.x * tw.y + g.y * tw.x;
        }
        H1[u] = acc;
    }
    __syncthreads();

#pragma unroll
    for (int u = tid; u < 1024; u += 256) {
        int y = u >> 5, z = u & 31;
        float2 acc = make_float2(0.f, 0.f);
#pragma unroll
        for (int kz = 0; kz < 16; kz++) {
            float2 g = H1[y * 16 + kz]; float2 tw = d_invX[z * 16 + kz];
            acc.x += g.x * tw.x - g.y * tw.y;
            acc.y += g.x * tw.y + g.y * tw.x;
        }
        g_fb[(size_t)bid * 1024 + u] = acc;       // [bo][kx*6+kt][y*32+z]
    }
}

// ---------------- fused: invX + invT(real) + pointwise + GELU ---------------
// block = (b, yz) ; 256 threads each own 2 (x,t) points
__global__ void __launch_bounds__(256) k_fused(const float* __restrict__ ww,
                                               const float* __restrict__ wb,
                                               int src, int do_gelu) {
    __shared__ float2 Gs[1920];   // [o][kx*6+kt]
    __shared__ float2 E[3840];    // [o][x*6+kt]
    __shared__ float  sww[400];
    __shared__ float  swb[NCH];
    __shared__ float2 itw[96];

    const float* hin  = src ? g_hB : g_hA;
    float*       hout = src ? g_hA : g_hB;

    int b = blockIdx.x >> 10;
    int yz = blockIdx.x & 1023;
    int tid = threadIdx.x;

    for (int q = tid; q < 1920; q += 256)
        Gs[q] = g_fb[((size_t)(b * 1920) + q) * 1024 + yz];
    for (int q = tid; q < 400; q += 256) sww[q] = ww[q];
    if (tid < NCH) swb[tid] = wb[tid];
    if (tid < 96)  itw[tid] = d_invT[tid];
    __syncthreads();

    // stage 1: invX  E[o][x][kt] = sum_kx Gs[o][kx][kt] * invX[x][kx]
#pragma unroll
    for (int u = tid; u < 3840; u += 256) {
        int o = u / 192; int r = u % 192;
        int x = r / 6, kt = r % 6;
        float2 acc = make_float2(0.f, 0.f);
        const float2* go = &Gs[o * 96 + kt];
#pragma unroll
        for (int kx = 0; kx < 16; kx++) {
            float2 g = go[kx * 6]; float2 tw = d_invX[x * 16 + kx];
            acc.x += g.x * tw.x - g.y * tw.y;
            acc.y += g.x * tw.y + g.y * tw.x;
        }
        E[u] = acc;
    }
    __syncthreads();

#pragma unroll
    for (int pt = 0; pt < 2; pt++) {
        int u = tid + pt * 256;
        int x = u >> 4, t = u & 15;
        size_t pidx = (size_t)x * 16384 + (size_t)yz * 16 + t;
        float hv[NCH];
#pragma unroll
        for (int i = 0; i < NCH; i++)
            hv[i] = hin[(size_t)(b * NCH + i) * NSP + pidx];
#pragma unroll 4
        for (int o = 0; o < NCH; o++) {
            float acc = swb[o];
#pragma unroll
            for (int i = 0; i < NCH; i++) acc += sww[o * NCH + i] * hv[i];
            float s = 0.f;
            const float2* eo = &E[o * 192 + x * 6];
#pragma unroll
            for (int k = 0; k < 6; k++) {
                float2 w = itw[t * 6 + k];
                float2 g = eo[k];
                s += g.x * w.x - g.y * w.y;
            }
            float v = acc + s;
            if (do_gelu) v = gelu_exact(v);
            hout[(size_t)(b * NCH + o) * NSP + pidx] = v;
        }
    }
}

// ---------------- head ------------------------------------------------------
__global__ void __launch_bounds__(256) k_head(const float* __restrict__ fc1w,
                                              const float* __restrict__ fc1b,
                                              const float* __restrict__ fc2w,
                                              const float* __restrict__ fc2b,
                                              float* __restrict__ out) {
    __shared__ float hs[NCH][256];
    __shared__ float w1[NCH * 128];
    __shared__ float b1[128], w2[128];

    int b = blockIdx.x >> 11;
    int pbase = (blockIdx.x & 2047) * 256;
    int tid = threadIdx.x;

#pragma unroll
    for (int i = 0; i < NCH; i++)
        hs[i][tid] = g_hA[(size_t)(b * NCH + i) * NSP + pbase + tid];
    for (int q = tid; q < NCH * 128; q += 256) w1[q] = fc1w[q];
    if (tid < 128) { b1[tid] = fc1b[tid]; w2[tid] = fc2w[tid]; }
    __syncthreads();

    float hv[NCH];
#pragma unroll
    for (int i = 0; i < NCH; i++) hv[i] = hs[i][tid];

    float acc = __ldg(&fc2b[0]);
#pragma unroll 4
    for (int j = 0; j < 128; j++) {
        float a = b1[j];
#pragma unroll
        for (int i = 0; i < NCH; i++) a += hv[i] * w1[i * 128 + j];
        a = gelu_exact(a);
        acc += a * w2[j];
    }
    out[(size_t)b * NSP + pbase + tid] = acc;
}

// ---------------- launch ----------------------------------------------------
extern "C" void kernel_launch(void* const* d_in, const int* in_sizes, int n_in,
                              void* d_out, int out_size) {
    const float* x     = (const float*)d_in[0];
    const float* fc0_w = (const float*)d_in[1];
    const float* fc0_b = (const float*)d_in[2];
    const float* sw    = (const float*)d_in[3];
    const float* ww    = (const float*)d_in[4];
    const float* wb    = (const float*)d_in[5];
    const float* fc1_w = (const float*)d_in[6];
    const float* fc1_b = (const float*)d_in[7];
    const float* fc2_w = (const float*)d_in[8];
    const float* fc2_b = (const float*)d_in[9];
    float* out = (float*)d_out;

    k_init<<<1, 512>>>();
    k_lift<<<4096, 256>>>(x, fc0_w, fc0_b);

    int src = 0;
    for (int l = 0; l < 4; l++) {
        k_fwdTZ<<<NB*NCH*32*4, 256>>>(src);        // 10240 blocks
        k_fwdYX<<<NB*NCH*96, 256>>>();             // 3840 blocks
        const float2* swl = (const float2*)sw + (size_t)l * 9830400;
        dim3 mg(96, 4);
        k_mult<<<mg, 256>>>(swl);
        k_invZY<<<NB*NCH*96, 256>>>();             // 3840 blocks
        k_fused<<<NB*1024, 256>>>(ww + l * 400, wb + l * NCH, src, (l < 3) ? 1 : 0);
        src ^= 1;
    }
    k_head<<<4096, 256>>>(fc1_w, fc1_b, fc2_w, fc2_b, out);
}

// round 4
// speedup vs baseline: 1.1995x; 1.1995x over previous
#include <cuda_runtime.h>
#include <math.h>

// ---------------- static scratch ----------------
#define NSP 524288            // 32*32*32*16 points per (b,c)
#define NCH 20
#define NB  2
#define NMODE 24576           // 16*16*16*6 kept modes

__device__ float  g_hA[NB*NCH*NSP];          // 84 MB
__device__ float  g_hB[NB*NCH*NSP];          // 84 MB
__device__ float2 g_fa[NB*NCH*16*6*1024];    // 31.5 MB : S1 [bc][kz*6+kt][x*32+y]
__device__ float2 g_fb[NB*NCH*16*6*1024];    // 31.5 MB : S2 [bo][kx*6+kt][y*32+z]
__device__ float2 g_fd[NB*NCH*NMODE];        // x_ft   at kept modes
__device__ float2 g_fe[NB*NCH*NMODE];        // out_ft at kept modes

// twiddle tables
__device__ float2 d_fwdX[512];   // [m(16)][x(32)]  e^{-2pi i k_m x/32},  k_m = m + (m>=8)*16
__device__ float2 d_fwdT[96];    // [k(6)][t(16)]   e^{-2pi i k t/16}
__device__ float2 d_invX[512];   // [x(32)][m(16)]  (1/32) e^{+2pi i k_m x/32}
__device__ float2 d_invT[96];    // [t(16)][k(6)]   ((k==0?1:2)/16) * (cos, sin)(+2pi k t/16)

__device__ __forceinline__ float gelu_exact(float v) {
    return 0.5f * v * (1.0f + erff(v * 0.70710678118654752f));
}

__global__ void k_init() {
    int tid = threadIdx.x;
    if (tid < 512) {
        int m = tid >> 5, x = tid & 31;
        int k = m + (m >= 8 ? 16 : 0);
        int ph = (k * x) & 31;
        float s, c; sincospif(-(float)ph / 16.0f, &s, &c);
        d_fwdX[tid] = make_float2(c, s);

        int z = tid >> 4, mm = tid & 15;
        int k2 = mm + (mm >= 8 ? 16 : 0);
        int ph2 = (k2 * z) & 31;
        float s2, c2; sincospif((float)ph2 / 16.0f, &s2, &c2);
        d_invX[tid] = make_float2(c2 * (1.0f/32.0f), s2 * (1.0f/32.0f));
    }
    if (tid < 96) {
        int k = tid / 16, t = tid & 15;
        int ph = (k * t) & 15;
        float s, c; sincospif(-(float)ph / 8.0f, &s, &c);
        d_fwdT[tid] = make_float2(c, s);

        int t2 = tid / 6, k2 = tid % 6;
        int ph2 = (k2 * t2) & 15;
        float wk = (k2 == 0 ? 1.0f : 2.0f) * (1.0f/16.0f);
        float s2, c2; sincospif((float)ph2 / 8.0f, &s2, &c2);
        d_invT[tid] = make_float2(wk * c2, wk * s2);
    }
}

// ---------------- lift ------------------------------------------------------
__global__ void __launch_bounds__(256) k_lift(const float* __restrict__ x,
                                              const float* __restrict__ w,
                                              const float* __restrict__ bias) {
    int tid = blockIdx.x * blockDim.x + threadIdx.x;
    if (tid >= NB * NSP) return;
    int b = tid / NSP, p = tid % NSP;
    float xi[5];
#pragma unroll
    for (int i = 0; i < 5; i++) xi[i] = x[(size_t)tid * 5 + i];
#pragma unroll
    for (int c = 0; c < NCH; c++) {
        float a = __ldg(&bias[c]);
#pragma unroll
        for (int i = 0; i < 5; i++) a += xi[i] * __ldg(&w[i * NCH + c]);
        g_hA[(size_t)(b * NCH + c) * NSP + p] = a;
    }
}

// ---------------- fwd T (16->6) + Z (32->16) fused -------------------------
// block = (bc, x, yq) ; 256 threads = (yl 8, z 32); warp spans z (coalesced h)
__global__ void __launch_bounds__(256) k_fwdTZ(int src) {
    __shared__ float2 st[8 * 6 * 33];            // [yl][kt][z] padded
    const float* h = src ? g_hB : g_hA;
    int bid = blockIdx.x;
    int yq = bid & 3, x = (bid >> 2) & 31, bc = bid >> 7;
    int tid = threadIdx.x;
    int yl = tid >> 5, z = tid & 31;

    const float4* p = (const float4*)(h + (size_t)bc * NSP + x * 16384 + (yq * 8 + yl) * 512 + z * 16);
    float v[16];
#pragma unroll
    for (int q = 0; q < 4; q++) {
        float4 f = p[q];
        v[q*4+0]=f.x; v[q*4+1]=f.y; v[q*4+2]=f.z; v[q*4+3]=f.w;
    }
    float2 a[6];
#pragma unroll
    for (int k = 0; k < 6; k++) a[k] = make_float2(0.f, 0.f);
#pragma unroll
    for (int t = 0; t < 16; t++) {
#pragma unroll
        for (int k = 0; k < 6; k++) {
            float2 w = d_fwdT[k * 16 + t];
            a[k].x += v[t] * w.x; a[k].y += v[t] * w.y;
        }
    }
#pragma unroll
    for (int k = 0; k < 6; k++) st[(yl * 6 + k) * 33 + z] = a[k];
    __syncthreads();

    // stage 2: 768 outputs (yl, kz*6+kt); 3 interleaved accumulators/thread
    int yl_i[3], kz_i[3], kt_i[3];
    const float2* row[3];
    float2 acc[3];
#pragma unroll
    for (int j = 0; j < 3; j++) {
        int w = tid + j * 256;
        yl_i[j] = w & 7; int kk = w >> 3;
        kt_i[j] = kk % 6; kz_i[j] = kk / 6;
        row[j] = &st[(yl_i[j] * 6 + kt_i[j]) * 33];
        acc[j] = make_float2(0.f, 0.f);
    }
#pragma unroll
    for (int zz = 0; zz < 32; zz++) {
#pragma unroll
        for (int j = 0; j < 3; j++) {
            float2 g = row[j][zz];
            float2 tw = d_fwdX[kz_i[j] * 32 + zz];
            acc[j].x += g.x * tw.x - g.y * tw.y;
            acc[j].y += g.x * tw.y + g.y * tw.x;
        }
    }
#pragma unroll
    for (int j = 0; j < 3; j++) {
        int kk = kz_i[j] * 6 + kt_i[j];
        g_fa[((size_t)(bc * 96) + kk) * 1024 + x * 32 + yq * 8 + yl_i[j]] = acc[j];
    }
}

// ---------------- fwd Y (32->16) + X (32->16) fused -------------------------
// block = (bc, slab-pair) ; 256 threads ; 2 slabs of [x][y]
__global__ void __launch_bounds__(256) k_fwdYX() {
    __shared__ float2 P[2048];   // [s][x][y]
    __shared__ float2 Q[1024];   // [s][x][ky]
    int bid = blockIdx.x;
    int sp = bid % 48, bc = bid / 48;
    int tid = threadIdx.x;
    const float2* s1 = g_fa + ((size_t)bc * 96 + sp * 2) * 1024;
#pragma unroll
    for (int q = 0; q < 8; q++) P[tid + q * 256] = s1[tid + q * 256];
    __syncthreads();

    // stage Y: 1024 outputs (s, x, ky); 4 interleaved accs
    {
        float2 acc[4]; int sx[4], ky[4];
#pragma unroll
        for (int j = 0; j < 4; j++) {
            int w = tid + j * 256;
            ky[j] = w & 15; sx[j] = w >> 4;   // sx = s*32 + x
            acc[j] = make_float2(0.f, 0.f);
        }
#pragma unroll
        for (int y = 0; y < 32; y++) {
#pragma unroll
            for (int j = 0; j < 4; j++) {
                float2 g = P[sx[j] * 32 + y];
                float2 tw = d_fwdX[ky[j] * 32 + y];
                acc[j].x += g.x * tw.x - g.y * tw.y;
                acc[j].y += g.x * tw.y + g.y * tw.x;
            }
        }
#pragma unroll
        for (int j = 0; j < 4; j++) Q[tid + j * 256] = acc[j];
    }
    __syncthreads();

    // stage X: 512 outputs (s, kx, ky); 2 interleaved accs
    {
        float2 acc[2]; int s_[2], kx_[2], ky_[2];
#pragma unroll
        for (int j = 0; j < 2; j++) {
            int w = tid + j * 256;
            s_[j] = w >> 8; int r = w & 255;
            kx_[j] = r >> 4; ky_[j] = r & 15;
            acc[j] = make_float2(0.f, 0.f);
        }
#pragma unroll
        for (int x = 0; x < 32; x++) {
#pragma unroll
            for (int j = 0; j < 2; j++) {
                float2 g = Q[s_[j] * 512 + x * 16 + ky_[j]];
                float2 tw = d_fwdX[kx_[j] * 32 + x];
                acc[j].x += g.x * tw.x - g.y * tw.y;
                acc[j].y += g.x * tw.y + g.y * tw.x;
            }
        }
#pragma unroll
        for (int j = 0; j < 2; j++) {
            int s = sp * 2 + s_[j];
            int kt = s % 6, kz = s / 6;
            int m = ((kx_[j] * 16 + ky_[j]) * 16 + kz) * 6 + kt;
            g_fd[(size_t)bc * NMODE + m] = acc[j];
        }
    }
}

// ---------------- spectral channel mix --------------------------------------
__global__ void __launch_bounds__(256) k_mult(const float2* __restrict__ swl) {
    int m = blockIdx.x * 256 + threadIdx.x;
    int ob = blockIdx.y * 5;
    int kt = m % 6; int r = m / 6;
    int kz = r & 15, ky = (r >> 4) & 15, kx = (r >> 8) & 15;
    int oct = ((kx >> 3) << 2) | ((ky >> 3) << 1) | (kz >> 3);
    int lm = (((kx & 7) * 8 + (ky & 7)) * 8 + (kz & 7)) * 6 + kt;
    const float2* wbase = swl + (size_t)oct * 1228800 + lm + (size_t)ob * 3072;

    float2 a0[5], a1[5];
#pragma unroll
    for (int o = 0; o < 5; o++) { a0[o] = make_float2(0.f,0.f); a1[o] = make_float2(0.f,0.f); }

    for (int i = 0; i < NCH; i++) {
        float2 x0 = __ldg(&g_fd[(size_t)i * NMODE + m]);
        float2 x1 = __ldg(&g_fd[(size_t)(NCH + i) * NMODE + m]);
        const float2* wp = wbase + (size_t)i * 61440;
#pragma unroll
        for (int o = 0; o < 5; o++) {
            float2 w = __ldg(&wp[o * 3072]);
            a0[o].x += w.x * x0.x - w.y * x0.y;
            a0[o].y += w.x * x0.y + w.y * x0.x;
            a1[o].x += w.x * x1.x - w.y * x1.y;
            a1[o].y += w.x * x1.y + w.y * x1.x;
        }
    }
#pragma unroll
    for (int o = 0; o < 5; o++) {
        g_fe[(size_t)(ob + o) * NMODE + m]        = a0[o];
        g_fe[(size_t)(NCH + ob + o) * NMODE + m]  = a1[o];
    }
}

// ---------------- inv Z (16->32) + Y (16->32) fused --------------------------
// block = (bo, slab-pair of kx*6+kt) ; 256 threads ; 2 slabs
__global__ void __launch_bounds__(256) k_invZY() {
    __shared__ float2 Gs[512];    // [s][ky][kz]
    __shared__ float2 H1[1024];   // [s][y][kz]
    int bid = blockIdx.x;
    int sp = bid % 48, bo = bid / 48;
    int tid = threadIdx.x;

#pragma unroll
    for (int j = 0; j < 2; j++) {
        int q = tid + j * 256;
        int i = q >> 8, v = q & 255;
        int s = sp * 2 + i;
        int kx = s / 6, kt = s % 6;
        Gs[q] = g_fe[(size_t)bo * NMODE + (size_t)(kx * 256 + v) * 6 + kt];
    }
    __syncthreads();

    // stage invZ-"ky" : H1[s][y][kz] = sum_ky Gs[s][ky][kz] * invX[y][ky]
    {
        float2 acc[4]; int i_[4], y_[4], kz_[4];
#pragma unroll
        for (int j = 0; j < 4; j++) {
            int w = tid + j * 256;
            i_[j] = w >> 9; int r = w & 511;
            y_[j] = r >> 4; kz_[j] = r & 15;
            acc[j] = make_float2(0.f, 0.f);
        }
#pragma unroll
        for (int ky = 0; ky < 16; ky++) {
#pragma unroll
            for (int j = 0; j < 4; j++) {
                float2 g = Gs[i_[j] * 256 + ky * 16 + kz_[j]];
                float2 tw = d_invX[y_[j] * 16 + ky];
                acc[j].x += g.x * tw.x - g.y * tw.y;
                acc[j].y += g.x * tw.y + g.y * tw.x;
            }
        }
#pragma unroll
        for (int j = 0; j < 4; j++) H1[tid + j * 256] = acc[j];
    }
    __syncthreads();

    // stage z: out[s][y][z] = sum_kz H1[s][y][kz] * invX[z][kz]
    {
        float2 acc[8]; int i_[8], y_[8], z_[8];
#pragma unroll
        for (int j = 0; j < 8; j++) {
            int w = tid + j * 256;
            i_[j] = w >> 10; int r = w & 1023;
            y_[j] = r >> 5; z_[j] = r & 31;
            acc[j] = make_float2(0.f, 0.f);
        }
#pragma unroll
        for (int kz = 0; kz < 16; kz++) {
#pragma unroll
            for (int j = 0; j < 8; j++) {
                float2 g = H1[i_[j] * 512 + y_[j] * 16 + kz];
                float2 tw = d_invX[z_[j] * 16 + kz];
                acc[j].x += g.x * tw.x - g.y * tw.y;
                acc[j].y += g.x * tw.y + g.y * tw.x;
            }
        }
#pragma unroll
        for (int j = 0; j < 8; j++) {
            int w = tid + j * 256;
            g_fb[((size_t)bo * 96 + sp * 2 + i_[j]) * 1024 + (w & 1023)] = acc[j];
        }
    }
}

// ---------------- fused: invX + invT(real) + pointwise + GELU ---------------
__global__ void __launch_bounds__(256) k_fused(const float* __restrict__ ww,
                                               const float* __restrict__ wb,
                                               int src, int do_gelu) {
    __shared__ float2 Gs[1920];   // [o][kx*6+kt]
    __shared__ float2 E[3840];    // [o][x*6+kt]
    __shared__ float  sww[400];
    __shared__ float  swb[NCH];
    __shared__ float2 itw[96];

    const float* hin  = src ? g_hB : g_hA;
    float*       hout = src ? g_hA : g_hB;

    int b = blockIdx.x >> 10;
    int yz = blockIdx.x & 1023;
    int tid = threadIdx.x;

    for (int q = tid; q < 1920; q += 256)
        Gs[q] = g_fb[((size_t)(b * 1920) + q) * 1024 + yz];
    for (int q = tid; q < 400; q += 256) sww[q] = ww[q];
    if (tid < NCH) swb[tid] = wb[tid];
    if (tid < 96)  itw[tid] = d_invT[tid];
    __syncthreads();

    // stage 1: invX  E[o][x][kt] = sum_kx Gs[o][kx*6+kt] * invX[x][kx]
    // 3840 outputs = 15/thread, grouped 3x5 interleaved
#pragma unroll
    for (int g = 0; g < 3; g++) {
        float2 acc[5]; const float2* go[5]; int x_[5];
#pragma unroll
        for (int j = 0; j < 5; j++) {
            int u = tid + (g * 5 + j) * 256;
            int o = u / 192; int r = u % 192;
            x_[j] = r / 6; int kt = r % 6;
            go[j] = &Gs[o * 96 + kt];
            acc[j] = make_float2(0.f, 0.f);
        }
#pragma unroll
        for (int kx = 0; kx < 16; kx++) {
#pragma unroll
            for (int j = 0; j < 5; j++) {
                float2 gg = go[j][kx * 6];
                float2 tw = d_invX[x_[j] * 16 + kx];
                acc[j].x += gg.x * tw.x - gg.y * tw.y;
                acc[j].y += gg.x * tw.y + gg.y * tw.x;
            }
        }
#pragma unroll
        for (int j = 0; j < 5; j++) E[tid + (g * 5 + j) * 256] = acc[j];
    }
    __syncthreads();

#pragma unroll
    for (int pt = 0; pt < 2; pt++) {
        int u = tid + pt * 256;
        int x = u >> 4, t = u & 15;
        size_t pidx = (size_t)x * 16384 + (size_t)yz * 16 + t;
        float hv[NCH];
#pragma unroll
        for (int i = 0; i < NCH; i++)
            hv[i] = hin[(size_t)(b * NCH + i) * NSP + pidx];
#pragma unroll 4
        for (int o = 0; o < NCH; o++) {
            float acc = swb[o];
#pragma unroll
            for (int i = 0; i < NCH; i++) acc += sww[o * NCH + i] * hv[i];
            float s = 0.f;
            const float2* eo = &E[o * 192 + x * 6];
#pragma unroll
            for (int k = 0; k < 6; k++) {
                float2 w = itw[t * 6 + k];
                float2 g = eo[k];
                s += g.x * w.x - g.y * w.y;
            }
            float v = acc + s;
            if (do_gelu) v = gelu_exact(v);
            hout[(size_t)(b * NCH + o) * NSP + pidx] = v;
        }
    }
}

// ---------------- head ------------------------------------------------------
__global__ void __launch_bounds__(256) k_head(const float* __restrict__ fc1w,
                                              const float* __restrict__ fc1b,
                                              const float* __restrict__ fc2w,
                                              const float* __restrict__ fc2b,
                                              float* __restrict__ out) {
    __shared__ float hs[NCH][256];
    __shared__ float w1[NCH * 128];
    __shared__ float b1[128], w2[128];

    int b = blockIdx.x >> 11;
    int pbase = (blockIdx.x & 2047) * 256;
    int tid = threadIdx.x;

#pragma unroll
    for (int i = 0; i < NCH; i++)
        hs[i][tid] = g_hA[(size_t)(b * NCH + i) * NSP + pbase + tid];
    for (int q = tid; q < NCH * 128; q += 256) w1[q] = fc1w[q];
    if (tid < 128) { b1[tid] = fc1b[tid]; w2[tid] = fc2w[tid]; }
    __syncthreads();

    float hv[NCH];
#pragma unroll
    for (int i = 0; i < NCH; i++) hv[i] = hs[i][tid];

    float acc = __ldg(&fc2b[0]);
#pragma unroll 4
    for (int j = 0; j < 128; j++) {
        float a = b1[j];
#pragma unroll
        for (int i = 0; i < NCH; i++) a += hv[i] * w1[i * 128 + j];
        a = gelu_exact(a);
        acc += a * w2[j];
    }
    out[(size_t)b * NSP + pbase + tid] = acc;
}

// ---------------- launch ----------------------------------------------------
extern "C" void kernel_launch(void* const* d_in, const int* in_sizes, int n_in,
                              void* d_out, int out_size) {
    const float* x     = (const float*)d_in[0];
    const float* fc0_w = (const float*)d_in[1];
    const float* fc0_b = (const float*)d_in[2];
    const float* sw    = (const float*)d_in[3];
    const float* ww    = (const float*)d_in[4];
    const float* wb    = (const float*)d_in[5];
    const float* fc1_w = (const float*)d_in[6];
    const float* fc1_b = (const float*)d_in[7];
    const float* fc2_w = (const float*)d_in[8];
    const float* fc2_b = (const float*)d_in[9];
    float* out = (float*)d_out;

    k_init<<<1, 512>>>();
    k_lift<<<4096, 256>>>(x, fc0_w, fc0_b);

    int src = 0;
    for (int l = 0; l < 4; l++) {
        k_fwdTZ<<<NB*NCH*32*4, 256>>>(src);        // 5120 blocks
        k_fwdYX<<<NB*NCH*48, 256>>>();             // 1920 blocks
        const float2* swl = (const float2*)sw + (size_t)l * 9830400;
        dim3 mg(96, 4);
        k_mult<<<mg, 256>>>(swl);
        k_invZY<<<NB*NCH*48, 256>>>();             // 1920 blocks
        k_fused<<<NB*1024, 256>>>(ww + l * 400, wb + l * NCH, src, (l < 3) ? 1 : 0);
        src ^= 1;
    }
    k_head<<<4096, 256>>>(fc1_w, fc1_b, fc2_w, fc2_b, out);
}

// round 5
// speedup vs baseline: 2.2120x; 1.8441x over previous
#include <cuda_runtime.h>
#include <math.h>

// ---------------- static scratch ----------------
#define NSP 524288            // 32*32*32*16 points per (b,c)
#define NCH 20
#define NB  2
#define NMODE 24576           // 16*16*16*6 kept modes

__device__ float  g_hA[NB*NCH*NSP];          // 84 MB
__device__ float  g_hB[NB*NCH*NSP];          // 84 MB
__device__ float2 g_fa[NB*NCH*96*1024];      // 31.5 MB : S1 [bc][kz*6+kt][x*32+y]
__device__ float2 g_fb[NB*NCH*96*1024];      // 31.5 MB : S2 [bo][kx*6+kt][y*32+z]
__device__ float2 g_fd[NB*NCH*NMODE];        // x_ft   at kept modes (m = ((kx*16+ky)*16+kz)*6+kt)
__device__ float2 g_fe[NB*NCH*NMODE];        // out_ft at kept modes

// cos(pi*j/16) table; sin(pi*j/16) = CSX[(j+24)&31]
__device__ static const float CSX[32] = {
     1.000000000f,  0.980785280f,  0.923879533f,  0.831469612f,
     0.707106781f,  0.555570233f,  0.382683432f,  0.195090322f,
     0.000000000f, -0.195090322f, -0.382683432f, -0.555570233f,
    -0.707106781f, -0.831469612f, -0.923879533f, -0.980785280f,
    -1.000000000f, -0.980785280f, -0.923879533f, -0.831469612f,
    -0.707106781f, -0.555570233f, -0.382683432f, -0.195090322f,
     0.000000000f,  0.195090322f,  0.382683432f,  0.555570233f,
     0.707106781f,  0.831469612f,  0.923879533f,  0.980785280f };

#define CSI(p) CSX[(p) & 31]
#define SNI(p) CSX[((p) + 24) & 31]

// invT table (runtime t index): [t(16)][k(6)]  ((k==0?1:2)/16)*(cos,sin)(+2pi k t/16)
__device__ float2 d_invT[96];

__device__ __forceinline__ float gelu_exact(float v) {
    return 0.5f * v * (1.0f + erff(v * 0.70710678118654752f));
}

__global__ void k_init() {
    int tid = threadIdx.x;
    if (tid < 96) {
        int t2 = tid / 6, k2 = tid % 6;
        int ph2 = (k2 * t2) & 15;
        float wk = (k2 == 0 ? 1.0f : 2.0f) * (1.0f/16.0f);
        float s2, c2; sincospif((float)ph2 / 8.0f, &s2, &c2);
        d_invT[tid] = make_float2(wk * c2, wk * s2);
    }
}

// ---------------- lift ------------------------------------------------------
__global__ void __launch_bounds__(256) k_lift(const float* __restrict__ x,
                                              const float* __restrict__ w,
                                              const float* __restrict__ bias) {
    int tid = blockIdx.x * blockDim.x + threadIdx.x;
    if (tid >= NB * NSP) return;
    int b = tid / NSP, p = tid % NSP;
    float xi[5];
#pragma unroll
    for (int i = 0; i < 5; i++) xi[i] = x[(size_t)tid * 5 + i];
#pragma unroll
    for (int c = 0; c < NCH; c++) {
        float a = __ldg(&bias[c]);
#pragma unroll
        for (int i = 0; i < 5; i++) a += xi[i] * __ldg(&w[i * NCH + c]);
        g_hA[(size_t)(b * NCH + c) * NSP + p] = a;
    }
}

// ---------------- fwd T (16->6) + Z (32->16), immediates --------------------
// block = (bc, x, yh) ; 128 threads
__global__ void __launch_bounds__(128) k_fwdTZ(int src) {
    __shared__ float2 st[6 * 16 * 33];            // [kt][yl][z] pad 33
    const float* h = src ? g_hB : g_hA;
    int bid = blockIdx.x;
    int yh = bid & 1, x = (bid >> 1) & 31, bc = bid >> 6;
    int tid = threadIdx.x;

    // stage T: 4 points per thread
#pragma unroll
    for (int q = 0; q < 4; q++) {
        int p = q * 128 + tid;
        int yl = p >> 5, z = p & 31;
        const float4* src4 = (const float4*)(h + (size_t)bc * NSP + x * 16384
                                             + (yh * 16 + yl) * 512 + z * 16);
        float v[16];
#pragma unroll
        for (int r = 0; r < 4; r++) {
            float4 f = src4[r];
            v[r*4+0]=f.x; v[r*4+1]=f.y; v[r*4+2]=f.z; v[r*4+3]=f.w;
        }
#pragma unroll
        for (int k = 0; k < 6; k++) {
            float ax = 0.f, ay = 0.f;
#pragma unroll
            for (int t = 0; t < 16; t++) {
                ax += v[t] * CSI(2*k*t);
                ay -= v[t] * SNI(2*k*t);
            }
            st[(k * 16 + yl) * 33 + z] = make_float2(ax, ay);
        }
    }
    __syncthreads();

    // stage Z: 96 threads = (kt 6, yl 16); 16 kz accumulators, immediates
    if (tid < 96) {
        int kt = tid >> 4, yl = tid & 15;
        float2 A[16];
#pragma unroll
        for (int m = 0; m < 16; m++) A[m] = make_float2(0.f, 0.f);
#pragma unroll
        for (int z = 0; z < 32; z++) {
            float2 g = st[(kt * 16 + yl) * 33 + z];
#pragma unroll
            for (int m = 0; m < 16; m++) {
                const int k = m + (m >= 8 ? 16 : 0);
                A[m].x += g.x * CSI(k*z) + g.y * SNI(k*z);
                A[m].y += g.y * CSI(k*z) - g.x * SNI(k*z);
            }
        }
#pragma unroll
        for (int m = 0; m < 16; m++)
            g_fa[((size_t)bc * 96 + m * 6 + kt) * 1024 + x * 32 + yh * 16 + yl] = A[m];
    }
}

// ---------------- fwd Y (32->16) + X (32->16), immediates -------------------
// block = (bc, slab-pair) ; 64 threads
__global__ void __launch_bounds__(64) k_fwdYX() {
    __shared__ float2 P[2 * 32 * 33];   // [s][x][y] pad 33
    __shared__ float2 Q[2 * 32 * 17];   // [s][x][ky] pad 17
    int bid = blockIdx.x;
    int sp = bid % 48, bc = bid / 48;
    int tid = threadIdx.x;
    const float2* s1 = g_fa + ((size_t)bc * 96 + sp * 2) * 1024;
#pragma unroll
    for (int q = 0; q < 32; q++) {
        int u = q * 64 + tid;
        int s = u >> 10, r = u & 1023;
        P[s * 1056 + (r >> 5) * 33 + (r & 31)] = s1[u];
    }
    __syncthreads();

    // stage Y: 64 threads = (s 2, x 32); 16 ky accs
    {
        int s = tid >> 5, x = tid & 31;
        float2 A[16];
#pragma unroll
        for (int m = 0; m < 16; m++) A[m] = make_float2(0.f, 0.f);
#pragma unroll
        for (int y = 0; y < 32; y++) {
            float2 g = P[s * 1056 + x * 33 + y];
#pragma unroll
            for (int m = 0; m < 16; m++) {
                const int k = m + (m >= 8 ? 16 : 0);
                A[m].x += g.x * CSI(k*y) + g.y * SNI(k*y);
                A[m].y += g.y * CSI(k*y) - g.x * SNI(k*y);
            }
        }
#pragma unroll
        for (int m = 0; m < 16; m++) Q[s * 544 + x * 17 + m] = A[m];
    }
    __syncthreads();

    // stage X: 32 threads = (s 2, ky 16); 16 kx accs
    if (tid < 32) {
        int s = tid >> 4, ky = tid & 15;
        float2 A[16];
#pragma unroll
        for (int m = 0; m < 16; m++) A[m] = make_float2(0.f, 0.f);
#pragma unroll
        for (int x = 0; x < 32; x++) {
            float2 g = Q[s * 544 + x * 17 + ky];
#pragma unroll
            for (int m = 0; m < 16; m++) {
                const int k = m + (m >= 8 ? 16 : 0);
                A[m].x += g.x * CSI(k*x) + g.y * SNI(k*x);
                A[m].y += g.y * CSI(k*x) - g.x * SNI(k*x);
            }
        }
        int sg = sp * 2 + s;
        int kz = sg / 6, kt = sg % 6;
#pragma unroll
        for (int m = 0; m < 16; m++)
            g_fd[(size_t)bc * NMODE + (size_t)(((m * 16 + ky) * 16 + kz) * 6 + kt)] = A[m];
    }
}

// ---------------- spectral channel mix --------------------------------------
__global__ void __launch_bounds__(256) k_mult(const float2* __restrict__ swl) {
    int m = blockIdx.x * 256 + threadIdx.x;
    int ob = blockIdx.y * 5;
    int kt = m % 6; int r = m / 6;
    int kz = r & 15, ky = (r >> 4) & 15, kx = (r >> 8) & 15;
    int oct = ((kx >> 3) << 2) | ((ky >> 3) << 1) | (kz >> 3);
    int lm = (((kx & 7) * 8 + (ky & 7)) * 8 + (kz & 7)) * 6 + kt;
    const float2* wbase = swl + (size_t)oct * 1228800 + lm + (size_t)ob * 3072;

    float2 a0[5], a1[5];
#pragma unroll
    for (int o = 0; o < 5; o++) { a0[o] = make_float2(0.f,0.f); a1[o] = make_float2(0.f,0.f); }

    for (int i = 0; i < NCH; i++) {
        float2 x0 = __ldg(&g_fd[(size_t)i * NMODE + m]);
        float2 x1 = __ldg(&g_fd[(size_t)(NCH + i) * NMODE + m]);
        const float2* wp = wbase + (size_t)i * 61440;
#pragma unroll
        for (int o = 0; o < 5; o++) {
            float2 w = __ldg(&wp[o * 3072]);
            a0[o].x += w.x * x0.x - w.y * x0.y;
            a0[o].y += w.x * x0.y + w.y * x0.x;
            a1[o].x += w.x * x1.x - w.y * x1.y;
            a1[o].y += w.x * x1.y + w.y * x1.x;
        }
    }
#pragma unroll
    for (int o = 0; o < 5; o++) {
        g_fe[(size_t)(ob + o) * NMODE + m]        = a0[o];
        g_fe[(size_t)(NCH + ob + o) * NMODE + m]  = a1[o];
    }
}

// ---------------- inv Y (16ky->32y) + Z (16kz->32z), immediates -------------
// block = (bo, slab-pair of (kx,kt)) ; 64 threads
__global__ void __launch_bounds__(64) k_invZY() {
    __shared__ float2 G[2 * 256];        // [s][ky*16+kz]
    __shared__ float2 H1[2 * 32 * 17];   // [s][y][kz] pad 17
    __shared__ float2 OUT[2 * 32 * 33];  // [s][y][z] pad 33
    int bid = blockIdx.x;
    int sp = bid % 48, bo = bid / 48;
    int tid = threadIdx.x;

#pragma unroll
    for (int q = 0; q < 8; q++) {
        int u = q * 64 + tid;
        int s = u >> 8, r = u & 255;
        int ky = r >> 4, kz = r & 15;
        int sg = sp * 2 + s;
        int kx = sg / 6, kt = sg % 6;
        G[u] = g_fe[(size_t)bo * NMODE + (size_t)(((kx * 16 + ky) * 16 + kz) * 6 + kt)];
    }
    __syncthreads();

    // stage invY: 32 threads = (s 2, kz 16); 32 y accs
    if (tid < 32) {
        int s = tid >> 4, kz = tid & 15;
        float2 A[32];
#pragma unroll
        for (int y = 0; y < 32; y++) A[y] = make_float2(0.f, 0.f);
#pragma unroll
        for (int m = 0; m < 16; m++) {
            const int k = m + (m >= 8 ? 16 : 0);
            float2 g = G[s * 256 + m * 16 + kz];
#pragma unroll
            for (int y = 0; y < 32; y++) {
                const float c = CSI(k*y) * (1.0f/32.0f);
                const float sn = SNI(k*y) * (1.0f/32.0f);
                A[y].x += g.x * c - g.y * sn;
                A[y].y += g.y * c + g.x * sn;
            }
        }
#pragma unroll
        for (int y = 0; y < 32; y++) H1[s * 544 + y * 17 + kz] = A[y];
    }
    __syncthreads();

    // stage invZ: 64 threads = (s 2, y 32); 32 z accs
    {
        int s = tid >> 5, y = tid & 31;
        float2 A[32];
#pragma unroll
        for (int z = 0; z < 32; z++) A[z] = make_float2(0.f, 0.f);
#pragma unroll
        for (int m = 0; m < 16; m++) {
            const int k = m + (m >= 8 ? 16 : 0);
            float2 g = H1[s * 544 + y * 17 + m];
#pragma unroll
            for (int z = 0; z < 32; z++) {
                const float c = CSI(k*z) * (1.0f/32.0f);
                const float sn = SNI(k*z) * (1.0f/32.0f);
                A[z].x += g.x * c - g.y * sn;
                A[z].y += g.y * c + g.x * sn;
            }
        }
#pragma unroll
        for (int z = 0; z < 32; z++) OUT[s * 1056 + y * 33 + z] = A[z];
    }
    __syncthreads();

#pragma unroll
    for (int q = 0; q < 32; q++) {
        int u = q * 64 + tid;
        int s = u >> 10, r = u & 1023;
        g_fb[((size_t)bo * 96 + sp * 2 + s) * 1024 + r] = OUT[s * 1056 + (r >> 5) * 33 + (r & 31)];
    }
}

// ---------------- fused: invX (imm) + invT + pointwise + GELU ---------------
__global__ void __launch_bounds__(256) k_fused(const float* __restrict__ ww,
                                               const float* __restrict__ wb,
                                               int src, int do_gelu) {
    __shared__ float2 Gs[1920];   // [o][kx*6+kt]
    __shared__ float2 E[3840];    // [o][x*6+kt]
    __shared__ float  sww[400];
    __shared__ float  swb[NCH];

    const float* hin  = src ? g_hB : g_hA;
    float*       hout = src ? g_hA : g_hB;

    int b = blockIdx.x >> 10;
    int yz = blockIdx.x & 1023;
    int tid = threadIdx.x;

    for (int q = tid; q < 1920; q += 256)
        Gs[q] = g_fb[((size_t)(b * 1920) + q) * 1024 + yz];
    for (int q = tid; q < 400; q += 256) sww[q] = ww[q];
    if (tid < NCH) swb[tid] = wb[tid];
    __syncthreads();

    // stage invX: 120 threads = (o 20, kt 6); 32 x accs, immediates
    if (tid < 120) {
        int o = tid / 6, kt = tid % 6;
        float2 A[32];
#pragma unroll
        for (int x = 0; x < 32; x++) A[x] = make_float2(0.f, 0.f);
#pragma unroll
        for (int m = 0; m < 16; m++) {
            const int k = m + (m >= 8 ? 16 : 0);
            float2 g = Gs[o * 96 + m * 6 + kt];
#pragma unroll
            for (int x = 0; x < 32; x++) {
                const float c = CSI(k*x) * (1.0f/32.0f);
                const float sn = SNI(k*x) * (1.0f/32.0f);
                A[x].x += g.x * c - g.y * sn;
                A[x].y += g.y * c + g.x * sn;
            }
        }
#pragma unroll
        for (int x = 0; x < 32; x++) E[o * 192 + x * 6 + kt] = A[x];
    }
    __syncthreads();

    // stage 2: 2 points per thread, processed together in the o-loop
    {
        int t = tid & 15, x0 = tid >> 4, x1 = x0 + 16;
        float2 wt[6];
#pragma unroll
        for (int k = 0; k < 6; k++) wt[k] = d_invT[t * 6 + k];

        size_t p0 = (size_t)x0 * 16384 + (size_t)yz * 16 + t;
        size_t p1 = (size_t)x1 * 16384 + (size_t)yz * 16 + t;
        float hv0[NCH], hv1[NCH];
#pragma unroll
        for (int i = 0; i < NCH; i++) {
            hv0[i] = hin[(size_t)(b * NCH + i) * NSP + p0];
            hv1[i] = hin[(size_t)(b * NCH + i) * NSP + p1];
        }
#pragma unroll 4
        for (int o = 0; o < NCH; o++) {
            float acc0 = swb[o], acc1 = acc0;
#pragma unroll
            for (int i = 0; i < NCH; i++) {
                float w = sww[o * NCH + i];
                acc0 += w * hv0[i];
                acc1 += w * hv1[i];
            }
            const float2* eo0 = &E[o * 192 + x0 * 6];
            const float2* eo1 = &E[o * 192 + x1 * 6];
            float s0 = 0.f, s1 = 0.f;
#pragma unroll
            for (int k = 0; k < 6; k++) {
                s0 += eo0[k].x * wt[k].x - eo0[k].y * wt[k].y;
                s1 += eo1[k].x * wt[k].x - eo1[k].y * wt[k].y;
            }
            float v0 = acc0 + s0, v1 = acc1 + s1;
            if (do_gelu) { v0 = gelu_exact(v0); v1 = gelu_exact(v1); }
            hout[(size_t)(b * NCH + o) * NSP + p0] = v0;
            hout[(size_t)(b * NCH + o) * NSP + p1] = v1;
        }
    }
}

// ---------------- head ------------------------------------------------------
__global__ void __launch_bounds__(256) k_head(const float* __restrict__ fc1w,
                                              const float* __restrict__ fc1b,
                                              const float* __restrict__ fc2w,
                                              const float* __restrict__ fc2b,
                                              float* __restrict__ out) {
    __shared__ float hs[NCH][256];
    __shared__ float w1[NCH * 128];
    __shared__ float b1[128], w2[128];

    int b = blockIdx.x >> 11;
    int pbase = (blockIdx.x & 2047) * 256;
    int tid = threadIdx.x;

#pragma unroll
    for (int i = 0; i < NCH; i++)
        hs[i][tid] = g_hA[(size_t)(b * NCH + i) * NSP + pbase + tid];
    for (int q = tid; q < NCH * 128; q += 256) w1[q] = fc1w[q];
    if (tid < 128) { b1[tid] = fc1b[tid]; w2[tid] = fc2w[tid]; }
    __syncthreads();

    float hv[NCH];
#pragma unroll
    for (int i = 0; i < NCH; i++) hv[i] = hs[i][tid];

    float acc = __ldg(&fc2b[0]);
#pragma unroll 4
    for (int j = 0; j < 128; j++) {
        float a = b1[j];
#pragma unroll
        for (int i = 0; i < NCH; i++) a += hv[i] * w1[i * 128 + j];
        a = gelu_exact(a);
        acc += a * w2[j];
    }
    out[(size_t)b * NSP + pbase + tid] = acc;
}

// ---------------- launch ----------------------------------------------------
extern "C" void kernel_launch(void* const* d_in, const int* in_sizes, int n_in,
                              void* d_out, int out_size) {
    const float* x     = (const float*)d_in[0];
    const float* fc0_w = (const float*)d_in[1];
    const float* fc0_b = (const float*)d_in[2];
    const float* sw    = (const float*)d_in[3];
    const float* ww    = (const float*)d_in[4];
    const float* wb    = (const float*)d_in[5];
    const float* fc1_w = (const float*)d_in[6];
    const float* fc1_b = (const float*)d_in[7];
    const float* fc2_w = (const float*)d_in[8];
    const float* fc2_b = (const float*)d_in[9];
    float* out = (float*)d_out;

    k_init<<<1, 128>>>();
    k_lift<<<4096, 256>>>(x, fc0_w, fc0_b);

    int src = 0;
    for (int l = 0; l < 4; l++) {
        k_fwdTZ<<<NB*NCH*64, 128>>>(src);          // 2560*2 blocks
        k_fwdYX<<<NB*NCH*48, 64>>>();              // 1920 blocks
        const float2* swl = (const float2*)sw + (size_t)l * 9830400;
        dim3 mg(96, 4);
        k_mult<<<mg, 256>>>(swl);
        k_invZY<<<NB*NCH*48, 64>>>();              // 1920 blocks
        k_fused<<<NB*1024, 256>>>(ww + l * 400, wb + l * NCH, src, (l < 3) ? 1 : 0);
        src ^= 1;
    }
    k_head<<<4096, 256>>>(fc1_w, fc1_b, fc2_w, fc2_b, out);
}

// round 6
// speedup vs baseline: 2.4319x; 1.0994x over previous
#include <cuda_runtime.h>
#include <math.h>

// ---------------- static scratch ----------------
#define NSP 524288            // 32*32*32*16 points per (b,c)
#define NCH 20
#define NB  2
#define NMODE 24576           // 16*16*16*6 kept modes

__device__ float  g_hA[NB*NCH*NSP];          // 84 MB
__device__ float  g_hB[NB*NCH*NSP];          // 84 MB
__device__ float2 g_fa[NB*NCH*96*1024];      // 31.5 MB : S1 [bc][kz*6+kt][x*32+y]
__device__ float2 g_fb[NB*NCH*96*1024];      // 31.5 MB : S2 [bo][kx*6+kt][y*32+z]
__device__ float2 g_fd[NB*NCH*NMODE];        // x_ft   at kept modes (m = ((kx*16+ky)*16+kz)*6+kt)
__device__ float2 g_fe[NB*NCH*NMODE];        // out_ft at kept modes

// cos(pi*j/16) table; sin(pi*j/16) = CSX[(j+24)&31]
__device__ static const float CSX[32] = {
     1.000000000f,  0.980785280f,  0.923879533f,  0.831469612f,
     0.707106781f,  0.555570233f,  0.382683432f,  0.195090322f,
     0.000000000f, -0.195090322f, -0.382683432f, -0.555570233f,
    -0.707106781f, -0.831469612f, -0.923879533f, -0.980785280f,
    -1.000000000f, -0.980785280f, -0.923879533f, -0.831469612f,
    -0.707106781f, -0.555570233f, -0.382683432f, -0.195090322f,
     0.000000000f,  0.195090322f,  0.382683432f,  0.555570233f,
     0.707106781f,  0.831469612f,  0.923879533f,  0.980785280f };

#define CSI(p) CSX[(p) & 31]
#define SNI(p) CSX[((p) + 24) & 31]
#define KOF(m) ((m) + ((m) >= 8 ? 16 : 0))

// invT table (runtime t index): [t(16)][k(6)]  ((k==0?1:2)/16)*(cos,sin)(+2pi k t/16)
__device__ float2 d_invT[96];

__device__ __forceinline__ float gelu_exact(float v) {
    return 0.5f * v * (1.0f + erff(v * 0.70710678118654752f));
}

__global__ void k_init() {
    int tid = threadIdx.x;
    if (tid < 96) {
        int t2 = tid / 6, k2 = tid % 6;
        int ph2 = (k2 * t2) & 15;
        float wk = (k2 == 0 ? 1.0f : 2.0f) * (1.0f/16.0f);
        float s2, c2; sincospif((float)ph2 / 8.0f, &s2, &c2);
        d_invT[tid] = make_float2(wk * c2, wk * s2);
    }
}

// ---------------- lift ------------------------------------------------------
__global__ void __launch_bounds__(256) k_lift(const float* __restrict__ x,
                                              const float* __restrict__ w,
                                              const float* __restrict__ bias) {
    int tid = blockIdx.x * blockDim.x + threadIdx.x;
    if (tid >= NB * NSP) return;
    int b = tid / NSP, p = tid % NSP;
    float xi[5];
#pragma unroll
    for (int i = 0; i < 5; i++) xi[i] = x[(size_t)tid * 5 + i];
#pragma unroll
    for (int c = 0; c < NCH; c++) {
        float a = __ldg(&bias[c]);
#pragma unroll
        for (int i = 0; i < 5; i++) a += xi[i] * __ldg(&w[i * NCH + c]);
        g_hA[(size_t)(b * NCH + c) * NSP + p] = a;
    }
}

// ---------------- fwd T (16->6) + Z (32->16), radix-2 imm -------------------
// block = (bc, x, yh) ; 128 threads
__global__ void __launch_bounds__(128) k_fwdTZ(int src) {
    __shared__ float2 st[6 * 16 * 33];            // [kt][yl][z] pad 33
    const float* h = src ? g_hB : g_hA;
    int bid = blockIdx.x;
    int yh = bid & 1, x = (bid >> 1) & 31, bc = bid >> 6;
    int tid = threadIdx.x;

    // stage T: 4 points per thread, radix-2 over t
#pragma unroll
    for (int q = 0; q < 4; q++) {
        int p = q * 128 + tid;
        int yl = p >> 5, z = p & 31;
        const float4* src4 = (const float4*)(h + (size_t)bc * NSP + x * 16384
                                             + (yh * 16 + yl) * 512 + z * 16);
        float v[16];
#pragma unroll
        for (int r = 0; r < 4; r++) {
            float4 f = src4[r];
            v[r*4+0]=f.x; v[r*4+1]=f.y; v[r*4+2]=f.z; v[r*4+3]=f.w;
        }
        float ue[8], uo[8];
#pragma unroll
        for (int t = 0; t < 8; t++) { ue[t] = v[t] + v[t+8]; uo[t] = v[t] - v[t+8]; }
#pragma unroll
        for (int k = 0; k < 6; k++) {
            const float* wsrc = (k & 1) ? uo : ue;
            float ax = 0.f, ay = 0.f;
#pragma unroll
            for (int t = 0; t < 8; t++) {
                ax += wsrc[t] * CSI(2*k*t);
                ay -= wsrc[t] * SNI(2*k*t);
            }
            st[(k * 16 + yl) * 33 + z] = make_float2(ax, ay);
        }
    }
    __syncthreads();

    // stage Z: 96 threads = (kt 6, yl 16); radix-2, 16 accs
    if (tid < 96) {
        int kt = tid >> 4, yl = tid & 15;
        float2 A[16];
#pragma unroll
        for (int m = 0; m < 16; m++) A[m] = make_float2(0.f, 0.f);
#pragma unroll
        for (int zp = 0; zp < 16; zp++) {
            float2 g0 = st[(kt * 16 + yl) * 33 + zp];
            float2 g1 = st[(kt * 16 + yl) * 33 + zp + 16];
            float2 u = make_float2(g0.x + g1.x, g0.y + g1.y);
            float2 v = make_float2(g0.x - g1.x, g0.y - g1.y);
#pragma unroll
            for (int mm = 0; mm < 8; mm++) {
                const int ke = KOF(2*mm);
                A[2*mm].x   += u.x * CSI(ke*zp) + u.y * SNI(ke*zp);
                A[2*mm].y   += u.y * CSI(ke*zp) - u.x * SNI(ke*zp);
                const int ko = KOF(2*mm+1);
                A[2*mm+1].x += v.x * CSI(ko*zp) + v.y * SNI(ko*zp);
                A[2*mm+1].y += v.y * CSI(ko*zp) - v.x * SNI(ko*zp);
            }
        }
#pragma unroll
        for (int m = 0; m < 16; m++)
            g_fa[((size_t)bc * 96 + m * 6 + kt) * 1024 + x * 32 + yh * 16 + yl] = A[m];
    }
}

// ---------------- fwd Y + X, radix-2 imm, 4 slabs / 128 threads -------------
__global__ void __launch_bounds__(128) k_fwdYX() {
    __shared__ float2 P[4 * 32 * 33];   // [s][x][y] pad 33 (Q written in place)
    int bid = blockIdx.x;
    int sp = bid % 24, bc = bid / 24;
    int tid = threadIdx.x;
    const float2* s1 = g_fa + ((size_t)bc * 96 + sp * 4) * 1024;
#pragma unroll
    for (int q = 0; q < 32; q++) {
        int u = q * 128 + tid;
        int s = u >> 10, r = u & 1023;
        P[s * 1056 + (r >> 5) * 33 + (r & 31)] = s1[u];
    }
    __syncthreads();

    // stage Y: (s 4, x 32) = 128; radix-2 over y, 16 ky accs; in-place write
    {
        int s = tid >> 5, x = tid & 31;
        float2 A[16];
#pragma unroll
        for (int m = 0; m < 16; m++) A[m] = make_float2(0.f, 0.f);
#pragma unroll
        for (int yp = 0; yp < 16; yp++) {
            float2 g0 = P[s * 1056 + x * 33 + yp];
            float2 g1 = P[s * 1056 + x * 33 + yp + 16];
            float2 u = make_float2(g0.x + g1.x, g0.y + g1.y);
            float2 v = make_float2(g0.x - g1.x, g0.y - g1.y);
#pragma unroll
            for (int mm = 0; mm < 8; mm++) {
                const int ke = KOF(2*mm);
                A[2*mm].x   += u.x * CSI(ke*yp) + u.y * SNI(ke*yp);
                A[2*mm].y   += u.y * CSI(ke*yp) - u.x * SNI(ke*yp);
                const int ko = KOF(2*mm+1);
                A[2*mm+1].x += v.x * CSI(ko*yp) + v.y * SNI(ko*yp);
                A[2*mm+1].y += v.y * CSI(ko*yp) - v.x * SNI(ko*yp);
            }
        }
#pragma unroll
        for (int m = 0; m < 16; m++) P[s * 1056 + x * 33 + m] = A[m];  // own row
    }
    __syncthreads();

    // stage X: (s 4, ky 16, par 2) = 128; mode-parity split with twiddle fold
    {
        int s = tid >> 5;
        int r = tid & 31; int ky = r >> 1; int par = r & 1;
        float2 A[8];
#pragma unroll
        for (int mm = 0; mm < 8; mm++) A[mm] = make_float2(0.f, 0.f);
#pragma unroll
        for (int xp = 0; xp < 16; xp++) {
            float2 g0 = P[s * 1056 + xp * 33 + ky];
            float2 g1 = P[s * 1056 + (xp + 16) * 33 + ky];
            float2 w;
            if (par) {
                float vx = g0.x - g1.x, vy = g0.y - g1.y;
                w.x = vx * CSI(xp) + vy * SNI(xp);
                w.y = vy * CSI(xp) - vx * SNI(xp);
            } else {
                w.x = g0.x + g1.x; w.y = g0.y + g1.y;
            }
#pragma unroll
            for (int mm = 0; mm < 8; mm++) {
                const int ke = KOF(2*mm);
                A[mm].x += w.x * CSI(ke*xp) + w.y * SNI(ke*xp);
                A[mm].y += w.y * CSI(ke*xp) - w.x * SNI(ke*xp);
            }
        }
        int sg = sp * 4 + s;
        int kz = sg / 6, kt = sg % 6;
#pragma unroll
        for (int mm = 0; mm < 8; mm++) {
            int m = 2 * mm + par;
            g_fd[(size_t)bc * NMODE + (size_t)(((m * 16 + ky) * 16 + kz) * 6 + kt)] = A[mm];
        }
    }
}

// ---------------- spectral channel mix --------------------------------------
__global__ void __launch_bounds__(256) k_mult(const float2* __restrict__ swl) {
    int m = blockIdx.x * 256 + threadIdx.x;
    int ob = blockIdx.y * 5;
    int kt = m % 6; int r = m / 6;
    int kz = r & 15, ky = (r >> 4) & 15, kx = (r >> 8) & 15;
    int oct = ((kx >> 3) << 2) | ((ky >> 3) << 1) | (kz >> 3);
    int lm = (((kx & 7) * 8 + (ky & 7)) * 8 + (kz & 7)) * 6 + kt;
    const float2* wbase = swl + (size_t)oct * 1228800 + lm + (size_t)ob * 3072;

    float2 a0[5], a1[5];
#pragma unroll
    for (int o = 0; o < 5; o++) { a0[o] = make_float2(0.f,0.f); a1[o] = make_float2(0.f,0.f); }

    for (int i = 0; i < NCH; i++) {
        float2 x0 = __ldg(&g_fd[(size_t)i * NMODE + m]);
        float2 x1 = __ldg(&g_fd[(size_t)(NCH + i) * NMODE + m]);
        const float2* wp = wbase + (size_t)i * 61440;
#pragma unroll
        for (int o = 0; o < 5; o++) {
            float2 w = __ldg(&wp[o * 3072]);
            a0[o].x += w.x * x0.x - w.y * x0.y;
            a0[o].y += w.x * x0.y + w.y * x0.x;
            a1[o].x += w.x * x1.x - w.y * x1.y;
            a1[o].y += w.x * x1.y + w.y * x1.x;
        }
    }
#pragma unroll
    for (int o = 0; o < 5; o++) {
        g_fe[(size_t)(ob + o) * NMODE + m]        = a0[o];
        g_fe[(size_t)(NCH + ob + o) * NMODE + m]  = a1[o];
    }
}

// ---------------- inv Y + Z, radix-2 imm (output pairing) -------------------
// block = (bo, slab-pair of (kx,kt)) ; 64 threads
__global__ void __launch_bounds__(64) k_invZY() {
    __shared__ float2 G[2 * 256];        // [s][ky*16+kz]
    __shared__ float2 H1[2 * 32 * 17];   // [s][y][kz] pad 17
    __shared__ float2 OUT[2 * 32 * 33];  // [s][y][z] pad 33
    int bid = blockIdx.x;
    int sp = bid % 48, bo = bid / 48;
    int tid = threadIdx.x;

#pragma unroll
    for (int q = 0; q < 8; q++) {
        int u = q * 64 + tid;
        int s = u >> 8, r = u & 255;
        int ky = r >> 4, kz = r & 15;
        int sg = sp * 2 + s;
        int kx = sg / 6, kt = sg % 6;
        G[u] = g_fe[(size_t)bo * NMODE + (size_t)(((kx * 16 + ky) * 16 + kz) * 6 + kt)];
    }
    __syncthreads();

    // stage invY: 32 threads = (s 2, kz 16); Se/So for y pairs
    if (tid < 32) {
        int s = tid >> 4, kz = tid & 15;
        float2 Se[16], So[16];
#pragma unroll
        for (int y = 0; y < 16; y++) { Se[y] = make_float2(0.f,0.f); So[y] = make_float2(0.f,0.f); }
#pragma unroll
        for (int m = 0; m < 16; m++) {
            const int k = KOF(m);
            float2 g = G[s * 256 + m * 16 + kz];
#pragma unroll
            for (int y = 0; y < 16; y++) {
                const float c = CSI(k*y) * (1.0f/32.0f);
                const float sn = SNI(k*y) * (1.0f/32.0f);
                float2& acc = (m & 1) ? So[y] : Se[y];
                acc.x += g.x * c - g.y * sn;
                acc.y += g.y * c + g.x * sn;
            }
        }
#pragma unroll
        for (int y = 0; y < 16; y++) {
            H1[s * 544 + y * 17 + kz]        = make_float2(Se[y].x + So[y].x, Se[y].y + So[y].y);
            H1[s * 544 + (y + 16) * 17 + kz] = make_float2(Se[y].x - So[y].x, Se[y].y - So[y].y);
        }
    }
    __syncthreads();

    // stage invZ: 64 threads = (s 2, y 32); Se/So for z pairs
    {
        int s = tid >> 5, y = tid & 31;
        float2 Se[16], So[16];
#pragma unroll
        for (int z = 0; z < 16; z++) { Se[z] = make_float2(0.f,0.f); So[z] = make_float2(0.f,0.f); }
#pragma unroll
        for (int m = 0; m < 16; m++) {
            const int k = KOF(m);
            float2 g = H1[s * 544 + y * 17 + m];
#pragma unroll
            for (int z = 0; z < 16; z++) {
                const float c = CSI(k*z) * (1.0f/32.0f);
                const float sn = SNI(k*z) * (1.0f/32.0f);
                float2& acc = (m & 1) ? So[z] : Se[z];
                acc.x += g.x * c - g.y * sn;
                acc.y += g.y * c + g.x * sn;
            }
        }
#pragma unroll
        for (int z = 0; z < 16; z++) {
            OUT[s * 1056 + y * 33 + z]      = make_float2(Se[z].x + So[z].x, Se[z].y + So[z].y);
            OUT[s * 1056 + y * 33 + z + 16] = make_float2(Se[z].x - So[z].x, Se[z].y - So[z].y);
        }
    }
    __syncthreads();

#pragma unroll
    for (int q = 0; q < 32; q++) {
        int u = q * 64 + tid;
        int s = u >> 10, r = u & 1023;
        g_fb[((size_t)bo * 96 + sp * 2 + s) * 1024 + r] = OUT[s * 1056 + (r >> 5) * 33 + (r & 31)];
    }
}

// ---------------- fused: invX (radix-2 imm) + invT + pointwise + GELU -------
__global__ void __launch_bounds__(256) k_fused(const float* __restrict__ ww,
                                               const float* __restrict__ wb,
                                               int src, int do_gelu) {
    __shared__ float2 Gs[1920];   // [o][kx*6+kt]
    __shared__ float2 E[3840];    // [o][x*6+kt]
    __shared__ float  sww[400];
    __shared__ float  swb[NCH];

    const float* hin  = src ? g_hB : g_hA;
    float*       hout = src ? g_hA : g_hB;

    int b = blockIdx.x >> 10;
    int yz = blockIdx.x & 1023;
    int tid = threadIdx.x;

    for (int q = tid; q < 1920; q += 256)
        Gs[q] = g_fb[((size_t)(b * 1920) + q) * 1024 + yz];
    for (int q = tid; q < 400; q += 256) sww[q] = ww[q];
    if (tid < NCH) swb[tid] = wb[tid];
    __syncthreads();

    // stage invX: 120 threads = (o 20, kt 6); Se/So for x pairs
    if (tid < 120) {
        int o = tid / 6, kt = tid % 6;
        float2 Se[16], So[16];
#pragma unroll
        for (int x = 0; x < 16; x++) { Se[x] = make_float2(0.f,0.f); So[x] = make_float2(0.f,0.f); }
#pragma unroll
        for (int m = 0; m < 16; m++) {
            const int k = KOF(m);
            float2 g = Gs[o * 96 + m * 6 + kt];
#pragma unroll
            for (int x = 0; x < 16; x++) {
                const float c = CSI(k*x) * (1.0f/32.0f);
                const float sn = SNI(k*x) * (1.0f/32.0f);
                float2& acc = (m & 1) ? So[x] : Se[x];
                acc.x += g.x * c - g.y * sn;
                acc.y += g.y * c + g.x * sn;
            }
        }
#pragma unroll
        for (int x = 0; x < 16; x++) {
            E[o * 192 + x * 6 + kt]        = make_float2(Se[x].x + So[x].x, Se[x].y + So[x].y);
            E[o * 192 + (x + 16) * 6 + kt] = make_float2(Se[x].x - So[x].x, Se[x].y - So[x].y);
        }
    }
    __syncthreads();

    // stage 2: 2 points per thread, processed together in the o-loop
    {
        int t = tid & 15, x0 = tid >> 4, x1 = x0 + 16;
        float2 wt[6];
#pragma unroll
        for (int k = 0; k < 6; k++) wt[k] = d_invT[t * 6 + k];

        size_t p0 = (size_t)x0 * 16384 + (size_t)yz * 16 + t;
        size_t p1 = (size_t)x1 * 16384 + (size_t)yz * 16 + t;
        float hv0[NCH], hv1[NCH];
#pragma unroll
        for (int i = 0; i < NCH; i++) {
            hv0[i] = hin[(size_t)(b * NCH + i) * NSP + p0];
            hv1[i] = hin[(size_t)(b * NCH + i) * NSP + p1];
        }
#pragma unroll 4
        for (int o = 0; o < NCH; o++) {
            float acc0 = swb[o], acc1 = acc0;
#pragma unroll
            for (int i = 0; i < NCH; i++) {
                float w = sww[o * NCH + i];
                acc0 += w * hv0[i];
                acc1 += w * hv1[i];
            }
            const float2* eo0 = &E[o * 192 + x0 * 6];
            const float2* eo1 = &E[o * 192 + x1 * 6];
            float s0 = 0.f, s1 = 0.f;
#pragma unroll
            for (int k = 0; k < 6; k++) {
                s0 += eo0[k].x * wt[k].x - eo0[k].y * wt[k].y;
                s1 += eo1[k].x * wt[k].x - eo1[k].y * wt[k].y;
            }
            float v0 = acc0 + s0, v1 = acc1 + s1;
            if (do_gelu) { v0 = gelu_exact(v0); v1 = gelu_exact(v1); }
            hout[(size_t)(b * NCH + o) * NSP + p0] = v0;
            hout[(size_t)(b * NCH + o) * NSP + p1] = v1;
        }
    }
}

// ---------------- head ------------------------------------------------------
__global__ void __launch_bounds__(256) k_head(const float* __restrict__ fc1w,
                                              const float* __restrict__ fc1b,
                                              const float* __restrict__ fc2w,
                                              const float* __restrict__ fc2b,
                                              float* __restrict__ out) {
    __shared__ float hs[NCH][256];
    __shared__ float w1[NCH * 128];
    __shared__ float b1[128], w2[128];

    int b = blockIdx.x >> 11;
    int pbase = (blockIdx.x & 2047) * 256;
    int tid = threadIdx.x;

#pragma unroll
    for (int i = 0; i < NCH; i++)
        hs[i][tid] = g_hA[(size_t)(b * NCH + i) * NSP + pbase + tid];
    for (int q = tid; q < NCH * 128; q += 256) w1[q] = fc1w[q];
    if (tid < 128) { b1[tid] = fc1b[tid]; w2[tid] = fc2w[tid]; }
    __syncthreads();

    float hv[NCH];
#pragma unroll
    for (int i = 0; i < NCH; i++) hv[i] = hs[i][tid];

    float acc = __ldg(&fc2b[0]);
#pragma unroll 4
    for (int j = 0; j < 128; j++) {
        float a = b1[j];
#pragma unroll
        for (int i = 0; i < NCH; i++) a += hv[i] * w1[i * 128 + j];
        a = gelu_exact(a);
        acc += a * w2[j];
    }
    out[(size_t)b * NSP + pbase + tid] = acc;
}

// ---------------- launch ----------------------------------------------------
extern "C" void kernel_launch(void* const* d_in, const int* in_sizes, int n_in,
                              void* d_out, int out_size) {
    const float* x     = (const float*)d_in[0];
    const float* fc0_w = (const float*)d_in[1];
    const float* fc0_b = (const float*)d_in[2];
    const float* sw    = (const float*)d_in[3];
    const float* ww    = (const float*)d_in[4];
    const float* wb    = (const float*)d_in[5];
    const float* fc1_w = (const float*)d_in[6];
    const float* fc1_b = (const float*)d_in[7];
    const float* fc2_w = (const float*)d_in[8];
    const float* fc2_b = (const float*)d_in[9];
    float* out = (float*)d_out;

    k_init<<<1, 128>>>();
    k_lift<<<4096, 256>>>(x, fc0_w, fc0_b);

    int src = 0;
    for (int l = 0; l < 4; l++) {
        k_fwdTZ<<<NB*NCH*64, 128>>>(src);
        k_fwdYX<<<NB*NCH*24, 128>>>();
        const float2* swl = (const float2*)sw + (size_t)l * 9830400;
        dim3 mg(96, 4);
        k_mult<<<mg, 256>>>(swl);
        k_invZY<<<NB*NCH*48, 64>>>();
        k_fused<<<NB*1024, 256>>>(ww + l * 400, wb + l * NCH, src, (l < 3) ? 1 : 0);
        src ^= 1;
    }
    k_head<<<4096, 256>>>(fc1_w, fc1_b, fc2_w, fc2_b, out);
}